// round 6
// baseline (speedup 1.0000x reference)
#include <cuda_runtime.h>
#include <cstdint>

// Problem dims (fixed by the dataset's setup_inputs)
#define C_   128
#define H_   56
#define W_   56
#define HW_  3136
#define TOTAL_ (16 * 128 * 3136)

#define NPAIR_BC  1568                    // HW/2 pixel-pairs per (b,c)
#define NPAIR_TOT (16 * 128 * NPAIR_BC)   // 3,211,264
#define TPB 256

// set.ge -> -1 (true) / 0 (false): single SASS FSET, no predication
__device__ __forceinline__ int setge(float a, float b) {
    int r;
    asm("set.ge.s32.f32 %0, %1, %2;" : "=r"(r) : "f"(a), "f"(b));
    return r;
}

__global__ __launch_bounds__(TPB)
void rrsvm_kernel(const float* __restrict__ x,
                  const float* __restrict__ s,
                  float* __restrict__ vout,
                  float* __restrict__ idxout)
{
    __shared__ float ssm[8][9];                       // per-warp rank weights
    __shared__ __align__(16) float stage[8][576];     // per-warp idx staging

    const int tid  = threadIdx.x;
    const int warp = tid >> 5;
    const int lane = tid & 31;
    const int t    = blockIdx.x * TPB + tid;          // pair id, exact grid

    const int bc = t / NPAIR_BC;                      // b*C + c
    const int q  = t - bc * NPAIR_BC;
    const int y  = q / 28;                            // output row
    const int xx = (q - y * 28) * 2;                  // left pixel col (even)

    // warp never straddles (b,c): NPAIR_BC = 1568 is a multiple of 32
    if (lane < 9)
        ssm[warp][lane] = __ldg(s + (bc & (C_ - 1)) * 9 + lane);
    __syncwarp();

    const float* __restrict__ xb = x + (size_t)bc * HW_;

    // 3 rows x 4 cols covering both 3x3 windows (zero padding = real values).
    // Middle pair is one aligned float2 (xx even); only the edges are scalar.
    float v[3][4];
#pragma unroll
    for (int rr = 0; rr < 3; rr++) {
        const int gy   = y + rr - 1;
        const bool rok = ((unsigned)gy < (unsigned)H_);
        const float* p = xb + gy * W_ + xx;
        float2 mid = make_float2(0.f, 0.f);
        if (rok) mid = *(const float2*)p;             // 8B aligned
        v[rr][1] = mid.x;
        v[rr][2] = mid.y;
        v[rr][0] = (rok & (xx > 0))  ? __ldg(p - 1) : 0.f;
        v[rr][3] = (rok & (xx < 54)) ? __ldg(p + 2) : 0.f;
    }

    // Stable-descending ranks for both windows, accumulated directly from
    // signed masks (m = -1 when earlier-index element wins; ties -> earlier
    // index, matching stable jnp.argsort(-p)). Masks die immediately.
    int r0[9], r1[9];
#pragma unroll
    for (int e = 0; e < 9; e++) { r0[e] = 8 - e; r1[e] = 8 - e; }

    // within-row pairs (a<b), skip unused (0,3)
#pragma unroll
    for (int rr = 0; rr < 3; rr++) {
#pragma unroll
        for (int a = 0; a < 4; a++) {
#pragma unroll
            for (int b = a + 1; b < 4; b++) {
                if (a == 0 && b == 3) continue;
                const int m = setge(v[rr][a], v[rr][b]);
                if (b <= 2) { r0[rr*3 + a]     += m; r0[rr*3 + b]     -= m; }
                if (a >= 1) { r1[rr*3 + a - 1] += m; r1[rr*3 + b - 1] -= m; }
            }
        }
    }
    // cross-row pairs: row pairs (0,1),(0,2),(1,2), all col combos except (0,3),(3,0)
#pragma unroll
    for (int rp = 0; rp < 3; rp++) {
        const int ra = (rp < 2) ? 0 : 1;
        const int rb = (rp == 0) ? 1 : 2;
#pragma unroll
        for (int a = 0; a < 4; a++) {
#pragma unroll
            for (int b = 0; b < 4; b++) {
                if ((a == 0 && b == 3) || (a == 3 && b == 0)) continue;
                const int m = setge(v[ra][a], v[rb][b]);   // (ra,·) earlier index
                if (a <= 2 && b <= 2) { r0[ra*3 + a]     += m; r0[rb*3 + b]     -= m; }
                if (a >= 1 && b >= 1) { r1[ra*3 + a - 1] += m; r1[rb*3 + b - 1] -= m; }
            }
        }
    }

    // Values (gather s via conflict-free LDS) + index scatter into warp stage.
    // Scatter addresses XOR bit-2 (16B) for the upper half-warp: lanes L and
    // L+16 otherwise alias banks (18*16 % 32 == 0). The XOR maps the upper
    // region [288,576) bijectively onto itself; readback undoes it below.
    float acc0 = 0.f, acc1 = 0.f;
    float* stg = stage[warp];
    const int b0 = lane * 18;
    const int sw = (lane & 16) >> 2;   // 0 or 4 words
#pragma unroll
    for (int e = 0; e < 9; e++) {
        acc0 = fmaf(v[e/3][e%3],     ssm[warp][r0[e]], acc0);
        acc1 = fmaf(v[e/3][e%3 + 1], ssm[warp][r1[e]], acc1);
        stg[(b0 + r0[e]) ^ sw]     = (float)e;    // constant payload, no I2F
        stg[(b0 + 9 + r1[e]) ^ sw] = (float)e;
    }

    if (vout) {
        float2 o = make_float2(acc0, acc1);
        *(float2*)(vout + (size_t)bc * HW_ + y * W_ + xx) = o;   // 8B aligned
    }

    __syncwarp();
    if (idxout) {
        // warp's 64 pixels own a contiguous 576-float (144 float4) span.
        // float4 index m >= 72 lives in the XOR-swizzled upper region:
        // word^4  <=>  float4idx^1.
        const float4* sf  = (const float4*)stage[warp];
        float4*       dst = (float4*)(idxout + (size_t)(t - lane) * 18);
#pragma unroll
        for (int k = 0; k < 4; k++) {
            const int m  = lane + 32 * k;
            const int mm = m ^ ((m >= 72) ? 1 : 0);
            dst[m] = sf[mm];
        }
        if (lane < 16) {
            const int m = lane + 128;          // always in upper region
            dst[m] = sf[m ^ 1];
        }
    }
}

extern "C" void kernel_launch(void* const* d_in, const int* in_sizes, int n_in,
                              void* d_out, int out_size) {
    const float* x = (const float*)d_in[0];
    const float* s = (const float*)d_in[1];

    float* vout   = (float*)d_out;
    float* idxout = nullptr;

    // Reference returns (out[B,C,H,W], indices[B,C,H,W,9]); harness concatenates.
    if (out_size >= 10 * TOTAL_) {
        idxout = (float*)d_out + TOTAL_;   // [out | indices]
    } else if (out_size == 9 * TOTAL_) {
        idxout = (float*)d_out;            // indices only
        vout   = nullptr;
    }

    const int blocks = NPAIR_TOT / TPB;    // exact: 12544
    rrsvm_kernel<<<blocks, TPB>>>(x, s, vout, idxout);
}

// round 8
// speedup vs baseline: 1.0653x; 1.0653x over previous
#include <cuda_runtime.h>
#include <cstdint>

// Problem dims (fixed by the dataset's setup_inputs)
#define C_   128
#define H_   56
#define W_   56
#define HW_  3136
#define TOTAL_ (16 * 128 * 3136)

#define NPAIR_BC  1568                    // HW/2 pixel-pairs per (b,c)
#define NPAIR_TOT (16 * 128 * NPAIR_BC)   // 3,211,264
#define TPB 256

// set.ge -> -1 (true) / 0 (false): single SASS FSET, no predication
__device__ __forceinline__ int setge(float a, float b) {
    int r;
    asm("set.ge.s32.f32 %0, %1, %2;" : "=r"(r) : "f"(a), "f"(b));
    return r;
}

// ---- packed-rank machinery -------------------------------------------------
// Patch cells (r, c): r in {0,1,2}, c in {0,1,2,3}. Window A = cols 0..2
// (element e_A = 3r+c), window B = cols 1..3 (e_B = 3r+c-1).
// 18 rank counters packed as bytes in 5 words:
//   w[r]: byte0 = RA(r,1), byte1 = RA(r,2), byte2 = RB(r,1), byte3 = RB(r,2)
//   wa:   byte r = RA(r,0)          wb: byte r = RB(r,3)
// Counter init = 8 - e; every prefix value stays in [0,8] (decrements are
// bounded by #later-elements, increments by #earlier), so bytes never
// under/overflow and whole-word add/sub of packed constants is exact.
// For a pair (X earlier, Y later), mask m in {0,-1}: counter(X) += m,
// counter(Y) -= m, applied PER WINDOW only when both cells are in it.
__host__ __device__ constexpr int kofA(int wi, int r, int c) {
    return (c == 1 && wi == r) ? 1
         : (c == 2 && wi == r) ? (1 << 8)
         : (c == 0 && wi == 3) ? (1 << (8 * r))
         : 0;
}
__host__ __device__ constexpr int kofB(int wi, int r, int c) {
    return (c == 1 && wi == r) ? (1 << 16)
         : (c == 2 && wi == r) ? (1 << 24)
         : (c == 3 && wi == 4) ? (1 << (8 * r))
         : 0;
}
__host__ __device__ constexpr int kpair(int wi, int rX, int cX, int rY, int cY) {
    return ((cX <= 2 && cY <= 2) ? (kofA(wi, rX, cX) - kofA(wi, rY, cY)) : 0)
         + ((cX >= 1 && cY >= 1) ? (kofB(wi, rX, cX) - kofB(wi, rY, cY)) : 0);
}

#define PAIR(rX, cX, rY, cY)                                                  \
    {                                                                         \
        const int m = setge(v[rX][cX], v[rY][cY]);                            \
        { constexpr int K = kpair(0, rX, cX, rY, cY); if (K) w0 += m * K; }   \
        { constexpr int K = kpair(1, rX, cX, rY, cY); if (K) w1 += m * K; }   \
        { constexpr int K = kpair(2, rX, cX, rY, cY); if (K) w2 += m * K; }   \
        { constexpr int K = kpair(3, rX, cX, rY, cY); if (K) wa += m * K; }   \
        { constexpr int K = kpair(4, rX, cX, rY, cY); if (K) wb += m * K; }   \
    }

// within-row pairs (skip (0,3): not co-windowed)
#define WROW(r) PAIR(r,0,r,1) PAIR(r,0,r,2) PAIR(r,1,r,2) PAIR(r,1,r,3) PAIR(r,2,r,3)
// cross-row pairs: all 4x4 col combos except (0,3) and (3,0)
#define XROW(ra, rb)                                                          \
    PAIR(ra,0,rb,0) PAIR(ra,0,rb,1) PAIR(ra,0,rb,2)                           \
    PAIR(ra,1,rb,0) PAIR(ra,1,rb,1) PAIR(ra,1,rb,2) PAIR(ra,1,rb,3)           \
    PAIR(ra,2,rb,0) PAIR(ra,2,rb,1) PAIR(ra,2,rb,2) PAIR(ra,2,rb,3)           \
    PAIR(ra,3,rb,1) PAIR(ra,3,rb,2) PAIR(ra,3,rb,3)

__global__ __launch_bounds__(TPB)
void rrsvm_kernel(const float* __restrict__ x,
                  const float* __restrict__ s,
                  float* __restrict__ vout,
                  float* __restrict__ idxout)
{
    __shared__ float ssm[8][9];                       // per-warp rank weights
    __shared__ __align__(16) float stage[8][576];     // per-warp idx staging

    const int tid  = threadIdx.x;
    const int warp = tid >> 5;
    const int lane = tid & 31;
    const int t    = blockIdx.x * TPB + tid;          // pair id, exact grid

    const int bc = t / NPAIR_BC;                      // b*C + c
    const int q  = t - bc * NPAIR_BC;
    const int y  = q / 28;                            // output row
    const int xx = (q - y * 28) * 2;                  // left pixel col (even)

    // warp never straddles (b,c): NPAIR_BC = 1568 is a multiple of 32
    if (lane < 9)
        ssm[warp][lane] = __ldg(s + (bc & (C_ - 1)) * 9 + lane);
    __syncwarp();

    const float* __restrict__ xb = x + (size_t)bc * HW_;
    const bool pl = (xx > 0);          // col xx-1 valid
    const bool pr = (xx < W_ - 2);     // col xx+2 valid

    // 3 rows x 4 cols covering both 3x3 windows (zero padding = real values)
    float v[3][4];
#pragma unroll
    for (int rr = 0; rr < 3; rr++) {
        const int gy   = y + rr - 1;
        const bool rok = ((unsigned)gy < (unsigned)H_);
        const float* p = xb + gy * W_ + xx;
        v[rr][0] = (rok & pl) ? __ldg(p - 1) : 0.f;
        v[rr][1] = rok        ? __ldg(p)     : 0.f;
        v[rr][2] = rok        ? __ldg(p + 1) : 0.f;
        v[rr][3] = (rok & pr) ? __ldg(p + 2) : 0.f;
    }

    // packed rank accumulation (init = 8 - e per counter, see layout above)
    int w0 = 7 | (6 << 8) | (8 << 16) | (7 << 24);
    int w1 = 4 | (3 << 8) | (5 << 16) | (4 << 24);
    int w2 = 1 | (0 << 8) | (2 << 16) | (1 << 24);
    int wa = 8 | (5 << 8) | (2 << 16);
    int wb = 6 | (3 << 8) | (0 << 16);

    WROW(0) WROW(1) WROW(2)
    XROW(0, 1) XROW(0, 2) XROW(1, 2)

    // extract the 9+9 ranks (bytes)
    int r0[9], r1[9];
    r0[0] =  wa        & 255;  r0[1] =  w0        & 255;  r0[2] = (w0 >> 8)  & 255;
    r0[3] = (wa >> 8)  & 255;  r0[4] =  w1        & 255;  r0[5] = (w1 >> 8)  & 255;
    r0[6] = (wa >> 16) & 255;  r0[7] =  w2        & 255;  r0[8] = (w2 >> 8)  & 255;
    r1[0] = (w0 >> 16) & 255;  r1[1] = (unsigned)w0 >> 24;  r1[2] =  wb        & 255;
    r1[3] = (w1 >> 16) & 255;  r1[4] = (unsigned)w1 >> 24;  r1[5] = (wb >> 8)  & 255;
    r1[6] = (w2 >> 16) & 255;  r1[7] = (unsigned)w2 >> 24;  r1[8] = (wb >> 16) & 255;

    // Values (gather s via conflict-free LDS) + index scatter into warp stage
    float acc0 = 0.f, acc1 = 0.f;
    float* st = &stage[warp][lane * 18];
#pragma unroll
    for (int e = 0; e < 9; e++) {
        acc0 = fmaf(v[e/3][e%3],     ssm[warp][r0[e]], acc0);
        acc1 = fmaf(v[e/3][e%3 + 1], ssm[warp][r1[e]], acc1);
        st[r0[e]]     = (float)e;    // constant payload, no I2F
        st[9 + r1[e]] = (float)e;
    }

    if (vout) {
        float2 o = make_float2(acc0, acc1);
        *(float2*)(vout + (size_t)bc * HW_ + y * W_ + xx) = o;   // 8B aligned
    }

    __syncwarp();
    if (idxout) {
        // warp's 64 pixels own a contiguous 576-float (144 float4) span
        const float4* sf  = (const float4*)stage[warp];
        float4*       dst = (float4*)(idxout + (size_t)(t - lane) * 18);
#pragma unroll
        for (int k = 0; k < 4; k++)
            dst[lane + 32 * k] = sf[lane + 32 * k];
        if (lane < 16)
            dst[lane + 128] = sf[lane + 128];
    }
}

extern "C" void kernel_launch(void* const* d_in, const int* in_sizes, int n_in,
                              void* d_out, int out_size) {
    const float* x = (const float*)d_in[0];
    const float* s = (const float*)d_in[1];

    float* vout   = (float*)d_out;
    float* idxout = nullptr;

    // Reference returns (out[B,C,H,W], indices[B,C,H,W,9]); harness concatenates.
    if (out_size >= 10 * TOTAL_) {
        idxout = (float*)d_out + TOTAL_;   // [out | indices]
    } else if (out_size == 9 * TOTAL_) {
        idxout = (float*)d_out;            // indices only
        vout   = nullptr;
    }

    const int blocks = NPAIR_TOT / TPB;    // exact: 12544
    rrsvm_kernel<<<blocks, TPB>>>(x, s, vout, idxout);
}